// round 1
// baseline (speedup 1.0000x reference)
#include <cuda_runtime.h>
#include <math.h>

// Problem constants (fixed by the dataset)
#define NMAX   100000
#define DIM    64
#define Hdim   14     // H = 2*LAT
#define HP     16     // padded feature width (float4-friendly)
#define PD     16     // P = (LAT+1)*R
#define LATC   7
#define OUTC   30     // 7 loc + 7 scale + 14 U + 2 m
#define SP_INV_1 0.5413248546129181f

// Scratch (static device globals -- no allocation allowed)
__device__ float4 g_Y1[NMAX * 4];
__device__ float4 g_Z1[NMAX * 4];
__device__ float4 g_Y2[NMAX * 4];
__device__ float4 g_Z2[NMAX * 4];

// Vector reduction (no return) -> REDG, avoids atom round-trip
__device__ __forceinline__ void red_add_f4(float4* addr, float4 v) {
    asm volatile("red.global.add.v4.f32 [%0], {%1,%2,%3,%4};"
                 :: "l"(addr), "f"(v.x), "f"(v.y), "f"(v.z), "f"(v.w)
                 : "memory");
}

// K1: Y1 = X @ W1 (N x 64 x 14), also zero Z1.
__global__ void k_gemm1(const float* __restrict__ X,
                        const float* __restrict__ W1, int N) {
    __shared__ float sW[DIM * Hdim];   // 64*14 = 896 floats
    for (int t = threadIdx.x; t < DIM * Hdim; t += blockDim.x)
        sW[t] = W1[t];
    __syncthreads();

    int i = blockIdx.x * blockDim.x + threadIdx.x;
    if (i >= N) return;

    const float4* x4 = (const float4*)(X + (long)i * DIM);
    float acc[Hdim];
#pragma unroll
    for (int j = 0; j < Hdim; ++j) acc[j] = 0.f;

#pragma unroll
    for (int k4 = 0; k4 < DIM / 4; ++k4) {
        float4 x = x4[k4];
        const float* w = &sW[k4 * 4 * Hdim];
#pragma unroll
        for (int j = 0; j < Hdim; ++j)
            acc[j] += x.x * w[j] + x.y * w[Hdim + j]
                    + x.z * w[2 * Hdim + j] + x.w * w[3 * Hdim + j];
    }

    g_Y1[i * 4 + 0] = make_float4(acc[0], acc[1], acc[2], acc[3]);
    g_Y1[i * 4 + 1] = make_float4(acc[4], acc[5], acc[6], acc[7]);
    g_Y1[i * 4 + 2] = make_float4(acc[8], acc[9], acc[10], acc[11]);
    g_Y1[i * 4 + 3] = make_float4(acc[12], acc[13], 0.f, 0.f);

    float4 z = make_float4(0.f, 0.f, 0.f, 0.f);
    g_Z1[i * 4 + 0] = z; g_Z1[i * 4 + 1] = z;
    g_Z1[i * 4 + 2] = z; g_Z1[i * 4 + 3] = z;
}

// K2/K4: SpMM over padded-16 features. layer 0: Y1->Z1, layer 1: Y2->Z2.
__global__ void k_spmm(const int* __restrict__ rows,
                       const int* __restrict__ cols,
                       const float* __restrict__ vals, int E, int layer) {
    int e = blockIdx.x * blockDim.x + threadIdx.x;
    if (e >= E) return;

    const float4* __restrict__ src = (layer == 0) ? g_Y1 : g_Y2;
    float4* dst = (layer == 0) ? g_Z1 : g_Z2;

    int r = rows[e];
    int c = cols[e];
    float v = vals[e];

    const float4* s = src + (long)c * 4;
    float4* d = dst + (long)r * 4;
#pragma unroll
    for (int q = 0; q < 4; ++q) {
        float4 sv = __ldg(&s[q]);
        red_add_f4(&d[q], make_float4(v * sv.x, v * sv.y, v * sv.z, v * sv.w));
    }
}

// K3: h1 = relu(Z1); Y2 = h1 @ W2 (14x14); zero Z2.
__global__ void k_mid(const float* __restrict__ W2, int N) {
    __shared__ float sW[Hdim * Hdim];  // 196
    for (int t = threadIdx.x; t < Hdim * Hdim; t += blockDim.x)
        sW[t] = W2[t];
    __syncthreads();

    int i = blockIdx.x * blockDim.x + threadIdx.x;
    if (i >= N) return;

    float h[Hdim];
    float4 a = g_Z1[i * 4 + 0];
    float4 b = g_Z1[i * 4 + 1];
    float4 cc = g_Z1[i * 4 + 2];
    float4 dd = g_Z1[i * 4 + 3];
    h[0] = fmaxf(a.x, 0.f);  h[1] = fmaxf(a.y, 0.f);
    h[2] = fmaxf(a.z, 0.f);  h[3] = fmaxf(a.w, 0.f);
    h[4] = fmaxf(b.x, 0.f);  h[5] = fmaxf(b.y, 0.f);
    h[6] = fmaxf(b.z, 0.f);  h[7] = fmaxf(b.w, 0.f);
    h[8] = fmaxf(cc.x, 0.f); h[9] = fmaxf(cc.y, 0.f);
    h[10] = fmaxf(cc.z, 0.f); h[11] = fmaxf(cc.w, 0.f);
    h[12] = fmaxf(dd.x, 0.f); h[13] = fmaxf(dd.y, 0.f);

    float acc[Hdim];
#pragma unroll
    for (int j = 0; j < Hdim; ++j) acc[j] = 0.f;
#pragma unroll
    for (int k = 0; k < Hdim; ++k) {
#pragma unroll
        for (int j = 0; j < Hdim; ++j)
            acc[j] += h[k] * sW[k * Hdim + j];
    }

    g_Y2[i * 4 + 0] = make_float4(acc[0], acc[1], acc[2], acc[3]);
    g_Y2[i * 4 + 1] = make_float4(acc[4], acc[5], acc[6], acc[7]);
    g_Y2[i * 4 + 2] = make_float4(acc[8], acc[9], acc[10], acc[11]);
    g_Y2[i * 4 + 3] = make_float4(acc[12], acc[13], 0.f, 0.f);

    float4 z = make_float4(0.f, 0.f, 0.f, 0.f);
    g_Z2[i * 4 + 0] = z; g_Z2[i * 4 + 1] = z;
    g_Z2[i * 4 + 2] = z; g_Z2[i * 4 + 3] = z;
}

__device__ __forceinline__ float softplus_f(float x) {
    // numerically stable: max(x,0) + log1p(exp(-|x|))
    return fmaxf(x, 0.f) + log1pf(expf(-fabsf(x)));
}

// K5: h2 = relu(Z2); heads; write 30 outputs per node.
__global__ void k_head(const float* __restrict__ Wd1,
                       const float* __restrict__ bd1,
                       const float* __restrict__ Wd2,
                       const float* __restrict__ bd2,
                       float* __restrict__ out, int N) {
    __shared__ float sW1[Hdim * Hdim];   // 196
    __shared__ float sB1[Hdim];
    __shared__ float sW2[Hdim * PD];     // 224
    __shared__ float sB2[PD];
    for (int t = threadIdx.x; t < Hdim * Hdim; t += blockDim.x) sW1[t] = Wd1[t];
    for (int t = threadIdx.x; t < Hdim * PD; t += blockDim.x)   sW2[t] = Wd2[t];
    if (threadIdx.x < Hdim) sB1[threadIdx.x] = bd1[threadIdx.x];
    if (threadIdx.x < PD)   sB2[threadIdx.x] = bd2[threadIdx.x];
    __syncthreads();

    int i = blockIdx.x * blockDim.x + threadIdx.x;
    if (i >= N) return;

    float h[Hdim];
    float4 a = g_Z2[i * 4 + 0];
    float4 b = g_Z2[i * 4 + 1];
    float4 cc = g_Z2[i * 4 + 2];
    float4 dd = g_Z2[i * 4 + 3];
    h[0] = fmaxf(a.x, 0.f);  h[1] = fmaxf(a.y, 0.f);
    h[2] = fmaxf(a.z, 0.f);  h[3] = fmaxf(a.w, 0.f);
    h[4] = fmaxf(b.x, 0.f);  h[5] = fmaxf(b.y, 0.f);
    h[6] = fmaxf(b.z, 0.f);  h[7] = fmaxf(b.w, 0.f);
    h[8] = fmaxf(cc.x, 0.f); h[9] = fmaxf(cc.y, 0.f);
    h[10] = fmaxf(cc.z, 0.f); h[11] = fmaxf(cc.w, 0.f);
    h[12] = fmaxf(dd.x, 0.f); h[13] = fmaxf(dd.y, 0.f);

    float pd[Hdim];
#pragma unroll
    for (int j = 0; j < Hdim; ++j) pd[j] = sB1[j];
#pragma unroll
    for (int k = 0; k < Hdim; ++k) {
#pragma unroll
        for (int j = 0; j < Hdim; ++j)
            pd[j] += h[k] * sW1[k * Hdim + j];
    }

    float pp[PD];
#pragma unroll
    for (int j = 0; j < PD; ++j) pp[j] = sB2[j];
#pragma unroll
    for (int k = 0; k < Hdim; ++k) {
#pragma unroll
        for (int j = 0; j < PD; ++j)
            pp[j] += h[k] * sW2[k * PD + j];
    }

    float* o = out + (long)i * OUTC;
#pragma unroll
    for (int j = 0; j < LATC; ++j)
        o[j] = tanhf(pd[j]);                                   // loc
#pragma unroll
    for (int j = 0; j < LATC; ++j)
        o[LATC + j] = softplus_f(tanhf(pd[LATC + j]) + SP_INV_1); // scale_diag
#pragma unroll
    for (int j = 0; j < Hdim; ++j)
        o[2 * LATC + j] = tanhf(pp[j]);                        // perturb_U (14)
#pragma unroll
    for (int j = 0; j < 2; ++j)
        o[2 * LATC + Hdim + j] = tanhf(pp[Hdim + j]);          // perturb_m (2)
}

extern "C" void kernel_launch(void* const* d_in, const int* in_sizes, int n_in,
                              void* d_out, int out_size) {
    const float* X    = (const float*)d_in[0];
    const int*   rows = (const int*)d_in[1];
    const int*   cols = (const int*)d_in[2];
    const float* vals = (const float*)d_in[3];
    const float* W1   = (const float*)d_in[4];
    const float* W2   = (const float*)d_in[5];
    const float* Wd1  = (const float*)d_in[6];
    const float* bd1  = (const float*)d_in[7];
    const float* Wd2  = (const float*)d_in[8];
    const float* bd2  = (const float*)d_in[9];
    float* out = (float*)d_out;

    int N = in_sizes[0] / DIM;
    int E = in_sizes[1];

    const int T = 256;
    int gN = (N + T - 1) / T;
    int gE = (E + T - 1) / T;

    k_gemm1<<<gN, T>>>(X, W1, N);
    k_spmm<<<gE, T>>>(rows, cols, vals, E, 0);
    k_mid<<<gN, T>>>(W2, N);
    k_spmm<<<gE, T>>>(rows, cols, vals, E, 1);
    k_head<<<gN, T>>>(Wd1, bd1, Wd2, bd2, out, N);
}

// round 2
// speedup vs baseline: 1.2684x; 1.2684x over previous
#include <cuda_runtime.h>
#include <math.h>

// Problem constants (fixed by the dataset)
#define NMAX   100000
#define EMAX   1000000
#define DIM    64
#define Hdim   14     // H = 2*LAT
#define PD     16     // P = (LAT+1)*R
#define LATC   7
#define OUTC   30     // 7 loc + 7 scale + 14 U + 2 m
#define SP_INV_1 0.5413248546129181f
#define NB     ((NMAX + 255) / 256)   // 391 scan blocks

// ---------------- scratch (static device globals; no allocation allowed) ---
__device__ float4 g_Y1[NMAX * 4];     // X@W1, padded 16 feats (last 2 = 0)
__device__ float4 g_Y2[NMAX * 4];     // relu(agg1)@W2, padded 16 feats
__device__ int    g_cnt[NMAX];        // degree
__device__ int    g_start[NMAX];      // CSR offsets (exclusive prefix)
__device__ int    g_cursor[NMAX];     // fill cursors
__device__ int    g_bsum[NB + 1];     // scan block sums
__device__ int2   g_edge[EMAX];       // (col, val_bits) bucketed by row

// ---------------- CSR build ------------------------------------------------
__global__ void k_zero(int N) {
    int i = blockIdx.x * blockDim.x + threadIdx.x;
    if (i < N) g_cnt[i] = 0;
}

__global__ void k_hist(const int* __restrict__ rows, int E) {
    int e = blockIdx.x * blockDim.x + threadIdx.x;
    if (e < E) atomicAdd(&g_cnt[rows[e]], 1);
}

// block-local exclusive scan of g_cnt -> g_start; block totals -> g_bsum
__global__ void k_scan1(int N) {
    __shared__ int s[256];
    int t = threadIdx.x;
    int i = blockIdx.x * 256 + t;
    int v = (i < N) ? g_cnt[i] : 0;
    s[t] = v;
    __syncthreads();
#pragma unroll
    for (int off = 1; off < 256; off <<= 1) {
        int x = (t >= off) ? s[t - off] : 0;
        __syncthreads();
        s[t] += x;
        __syncthreads();
    }
    if (i < N) g_start[i] = s[t] - v;          // exclusive within block
    if (t == 255) g_bsum[blockIdx.x] = s[255]; // block total
}

// single-block exclusive scan of block sums (nb <= 1024)
__global__ void k_scan2(int nb) {
    __shared__ int s[1024];
    int t = threadIdx.x;
    int v = (t < nb) ? g_bsum[t] : 0;
    s[t] = v;
    __syncthreads();
#pragma unroll
    for (int off = 1; off < 1024; off <<= 1) {
        int x = (t >= off) ? s[t - off] : 0;
        __syncthreads();
        s[t] += x;
        __syncthreads();
    }
    if (t < nb) g_bsum[t] = s[t] - v;          // exclusive
}

__global__ void k_scan3(int N) {
    int i = blockIdx.x * blockDim.x + threadIdx.x;
    if (i < N) {
        int v = g_start[i] + g_bsum[i >> 8];
        g_start[i]  = v;
        g_cursor[i] = v;
    }
}

__global__ void k_fill(const int* __restrict__ rows, const int* __restrict__ cols,
                       const float* __restrict__ vals, int E) {
    int e = blockIdx.x * blockDim.x + threadIdx.x;
    if (e >= E) return;
    int r = rows[e];
    int pos = atomicAdd(&g_cursor[r], 1);
    g_edge[pos] = make_int2(cols[e], __float_as_int(vals[e]));
}

// ---------------- K1: Y1 = X @ W1 (N x 64 x 14) ----------------------------
__global__ void k_gemm1(const float* __restrict__ X,
                        const float* __restrict__ W1, int N) {
    __shared__ float sW[DIM * Hdim];   // 896 floats
    for (int t = threadIdx.x; t < DIM * Hdim; t += blockDim.x)
        sW[t] = W1[t];
    __syncthreads();

    int i = blockIdx.x * blockDim.x + threadIdx.x;
    if (i >= N) return;

    const float4* x4 = (const float4*)(X + (long)i * DIM);
    float acc[Hdim];
#pragma unroll
    for (int j = 0; j < Hdim; ++j) acc[j] = 0.f;

#pragma unroll
    for (int k4 = 0; k4 < DIM / 4; ++k4) {
        float4 x = x4[k4];
        const float* w = &sW[k4 * 4 * Hdim];
#pragma unroll
        for (int j = 0; j < Hdim; ++j)
            acc[j] += x.x * w[j] + x.y * w[Hdim + j]
                    + x.z * w[2 * Hdim + j] + x.w * w[3 * Hdim + j];
    }

    g_Y1[i * 4 + 0] = make_float4(acc[0], acc[1], acc[2], acc[3]);
    g_Y1[i * 4 + 1] = make_float4(acc[4], acc[5], acc[6], acc[7]);
    g_Y1[i * 4 + 2] = make_float4(acc[8], acc[9], acc[10], acc[11]);
    g_Y1[i * 4 + 3] = make_float4(acc[12], acc[13], 0.f, 0.f);
}

// ---------------- helpers ---------------------------------------------------
__device__ __forceinline__ float ftanh(float x) {
    x = fminf(fmaxf(x, -15.f), 15.f);
    float e = __expf(2.f * x);
    return (e - 1.f) / (e + 1.f);
}
__device__ __forceinline__ float fsoftplus(float x) {
    // input range here is [-0.46, 1.54]; plain form is safe & accurate
    return log1pf(__expf(x));
}

// gather-aggregate one float4 chunk (q) of node i via CSR
__device__ __forceinline__ float4 csr_agg(const float4* __restrict__ src,
                                          int i, int q) {
    int start = g_start[i];
    int end   = start + g_cnt[i];
    float4 acc = make_float4(0.f, 0.f, 0.f, 0.f);
    for (int e = start; e < end; ++e) {
        int2 ed = __ldg(&g_edge[e]);
        float v = __int_as_float(ed.y);
        float4 s = __ldg(&src[(long)ed.x * 4 + q]);
        acc.x += v * s.x; acc.y += v * s.y;
        acc.z += v * s.z; acc.w += v * s.w;
    }
    return acc;
}

// broadcast the 16 h-values of this 4-lane group into h[16]
__device__ __forceinline__ void group_bcast(float4 acc, float* h, int lane) {
    int base = lane & ~3;
#pragma unroll
    for (int sq = 0; sq < 4; ++sq) {
        h[4 * sq + 0] = __shfl_sync(0xffffffffu, acc.x, base + sq);
        h[4 * sq + 1] = __shfl_sync(0xffffffffu, acc.y, base + sq);
        h[4 * sq + 2] = __shfl_sync(0xffffffffu, acc.z, base + sq);
        h[4 * sq + 3] = __shfl_sync(0xffffffffu, acc.w, base + sq);
    }
}

// ---------------- K2: Y2 = relu(agg(Y1)) @ W2 (fused) ----------------------
__global__ void k_agg1(const float* __restrict__ W2, int N) {
    __shared__ float sW[Hdim * 16];    // W2 padded to 14x16, pads = 0
    for (int t = threadIdx.x; t < Hdim * 16; t += blockDim.x) {
        int k = t >> 4, j = t & 15;
        sW[t] = (j < Hdim) ? W2[k * Hdim + j] : 0.f;
    }
    __syncthreads();

    int tid = blockIdx.x * blockDim.x + threadIdx.x;
    int i = tid >> 2, q = tid & 3;
    bool valid = (i < N);
    int ic = valid ? i : 0;

    float4 acc = make_float4(0.f, 0.f, 0.f, 0.f);
    if (valid) acc = csr_agg(g_Y1, ic, q);

    // relu (pads stay 0)
    acc.x = fmaxf(acc.x, 0.f); acc.y = fmaxf(acc.y, 0.f);
    acc.z = fmaxf(acc.z, 0.f); acc.w = fmaxf(acc.w, 0.f);

    float h[16];
    group_bcast(acc, h, threadIdx.x & 31);

    int j0 = q * 4;
    float y[4] = {0.f, 0.f, 0.f, 0.f};
#pragma unroll
    for (int k = 0; k < Hdim; ++k) {
        float hk = h[k];
#pragma unroll
        for (int d = 0; d < 4; ++d)
            y[d] += hk * sW[k * 16 + j0 + d];
    }

    if (valid)
        g_Y2[(long)i * 4 + q] = make_float4(y[0], y[1], y[2], y[3]);
}

// ---------------- K3: agg(Y2) -> relu -> heads -> out (fused) --------------
__global__ void k_agg2(const float* __restrict__ Wd1, const float* __restrict__ bd1,
                       const float* __restrict__ Wd2, const float* __restrict__ bd2,
                       float* __restrict__ out, int N) {
    __shared__ float sW1[Hdim * 16];   // Wd1 padded 14x16
    __shared__ float sW2[Hdim * 16];   // Wd2 14x16 (natural)
    __shared__ float sB1[16];
    __shared__ float sB2[16];
    for (int t = threadIdx.x; t < Hdim * 16; t += blockDim.x) {
        int k = t >> 4, j = t & 15;
        sW1[t] = (j < Hdim) ? Wd1[k * Hdim + j] : 0.f;
        sW2[t] = Wd2[k * PD + j];
    }
    if (threadIdx.x < 16) {
        sB1[threadIdx.x] = (threadIdx.x < Hdim) ? bd1[threadIdx.x] : 0.f;
        sB2[threadIdx.x] = bd2[threadIdx.x];
    }
    __syncthreads();

    int tid = blockIdx.x * blockDim.x + threadIdx.x;
    int i = tid >> 2, q = tid & 3;
    bool valid = (i < N);
    int ic = valid ? i : 0;

    float4 acc = make_float4(0.f, 0.f, 0.f, 0.f);
    if (valid) acc = csr_agg(g_Y2, ic, q);

    acc.x = fmaxf(acc.x, 0.f); acc.y = fmaxf(acc.y, 0.f);
    acc.z = fmaxf(acc.z, 0.f); acc.w = fmaxf(acc.w, 0.f);

    float h[16];
    group_bcast(acc, h, threadIdx.x & 31);

    int j0 = q * 4;
    float pd[4], pp[4];
#pragma unroll
    for (int d = 0; d < 4; ++d) { pd[d] = sB1[j0 + d]; pp[d] = sB2[j0 + d]; }
#pragma unroll
    for (int k = 0; k < Hdim; ++k) {
        float hk = h[k];
#pragma unroll
        for (int d = 0; d < 4; ++d) {
            pd[d] += hk * sW1[k * 16 + j0 + d];
            pp[d] += hk * sW2[k * 16 + j0 + d];
        }
    }

    if (valid) {
        float* o = out + (long)i * OUTC;
#pragma unroll
        for (int d = 0; d < 4; ++d) {
            int j = j0 + d;
            if (j < Hdim) {
                float t = ftanh(pd[d]);
                o[j] = (j < LATC) ? t : fsoftplus(t + SP_INV_1);
            }
            o[Hdim + j] = ftanh(pp[d]);   // 16 perturb outputs: U(14) + m(2)
        }
    }
}

// ---------------- launch ----------------------------------------------------
extern "C" void kernel_launch(void* const* d_in, const int* in_sizes, int n_in,
                              void* d_out, int out_size) {
    const float* X    = (const float*)d_in[0];
    const int*   rows = (const int*)d_in[1];
    const int*   cols = (const int*)d_in[2];
    const float* vals = (const float*)d_in[3];
    const float* W1   = (const float*)d_in[4];
    const float* W2   = (const float*)d_in[5];
    const float* Wd1  = (const float*)d_in[6];
    const float* bd1  = (const float*)d_in[7];
    const float* Wd2  = (const float*)d_in[8];
    const float* bd2  = (const float*)d_in[9];
    float* out = (float*)d_out;

    int N = in_sizes[0] / DIM;
    int E = in_sizes[1];

    const int T = 256;
    int gN  = (N + T - 1) / T;          // node-grid
    int gE  = (E + T - 1) / T;          // edge-grid
    int g4N = (N * 4 + T - 1) / T;      // 4-threads-per-node grid
    int nb  = (N + 255) / 256;          // scan blocks

    // CSR build
    k_zero <<<gN, T>>>(N);
    k_hist <<<gE, T>>>(rows, E);
    k_scan1<<<nb, 256>>>(N);
    k_scan2<<<1, 1024>>>(nb);
    k_scan3<<<gN, T>>>(N);
    k_fill <<<gE, T>>>(rows, cols, vals, E);

    // pipeline
    k_gemm1<<<gN, T>>>(X, W1, N);
    k_agg1 <<<g4N, T>>>(W2, N);
    k_agg2 <<<g4N, T>>>(Wd1, bd1, Wd2, bd2, out, N);
}